// round 2
// baseline (speedup 1.0000x reference)
#include <cuda_runtime.h>
#include <cstdint>

// Problem constants
#define MTOT   32768      // B*S = 8*4096
#define DM     512        // d_model = K_DIM = N
#define HEADS  8
#define HD     64
#define WSZ    128        // window size
#define NWIN   256        // MTOT / WSZ

// ---------------------------------------------------------------------------
// Scratch (device globals; no runtime allocation allowed)
// ---------------------------------------------------------------------------
__device__ float g_q [MTOT * DM];
__device__ float g_k [MTOT * DM];
__device__ float g_v [MTOT * DM];
__device__ float g_ao[MTOT * DM];

// ---------------------------------------------------------------------------
// GEMM: C[m][n] = sum_k A[m][k] * W[n][k] + bias[n]
// A: M x K row-major, W: N x K row-major (torch Linear layout), C: M x N
// 128x128 tile, BK=8, 256 threads, 8x8 register blocking.
// ---------------------------------------------------------------------------
__global__ __launch_bounds__(256) void gemm_tn(
    const float* __restrict__ A, const float* __restrict__ W,
    const float* __restrict__ bias, float* __restrict__ C,
    int M, int N, int K)
{
    __shared__ float As[8][132];
    __shared__ float Bs[8][132];

    const int t    = threadIdx.x;
    const int lrow = t >> 1;          // 0..127
    const int lseg = (t & 1) << 2;    // 0 or 4
    const int tm0  = (t >> 4) << 3;   // 0..120 step 8
    const int tn0  = (t & 15) << 3;

    const float* Ag = A + (size_t)(blockIdx.y * 128 + lrow) * K + lseg;
    const float* Wg = W + (size_t)(blockIdx.x * 128 + lrow) * K + lseg;

    float acc[8][8];
#pragma unroll
    for (int i = 0; i < 8; i++)
#pragma unroll
        for (int j = 0; j < 8; j++) acc[i][j] = 0.f;

    for (int k0 = 0; k0 < K; k0 += 8) {
        float4 av = *(const float4*)(Ag + k0);
        float4 wv = *(const float4*)(Wg + k0);
        As[lseg + 0][lrow] = av.x;
        As[lseg + 1][lrow] = av.y;
        As[lseg + 2][lrow] = av.z;
        As[lseg + 3][lrow] = av.w;
        Bs[lseg + 0][lrow] = wv.x;
        Bs[lseg + 1][lrow] = wv.y;
        Bs[lseg + 2][lrow] = wv.z;
        Bs[lseg + 3][lrow] = wv.w;
        __syncthreads();

#pragma unroll
        for (int kk = 0; kk < 8; kk++) {
            float a[8], b[8];
            *(float4*)&a[0] = *(const float4*)&As[kk][tm0];
            *(float4*)&a[4] = *(const float4*)&As[kk][tm0 + 4];
            *(float4*)&b[0] = *(const float4*)&Bs[kk][tn0];
            *(float4*)&b[4] = *(const float4*)&Bs[kk][tn0 + 4];
#pragma unroll
            for (int i = 0; i < 8; i++)
#pragma unroll
                for (int j = 0; j < 8; j++)
                    acc[i][j] = fmaf(a[i], b[j], acc[i][j]);
        }
        __syncthreads();
    }

    const int m0 = blockIdx.y * 128 + tm0;
    const int n0 = blockIdx.x * 128 + tn0;
    float bl[8];
    *(float4*)&bl[0] = *(const float4*)(bias + n0);
    *(float4*)&bl[4] = *(const float4*)(bias + n0 + 4);

#pragma unroll
    for (int i = 0; i < 8; i++) {
        float4 o0 = make_float4(acc[i][0] + bl[0], acc[i][1] + bl[1],
                                acc[i][2] + bl[2], acc[i][3] + bl[3]);
        float4 o1 = make_float4(acc[i][4] + bl[4], acc[i][5] + bl[5],
                                acc[i][6] + bl[6], acc[i][7] + bl[7]);
        float* cp = C + (size_t)(m0 + i) * N + n0;
        *(float4*)(cp)     = o0;
        *(float4*)(cp + 4) = o1;
    }
}

// ---------------------------------------------------------------------------
// Windowed attention: one CTA per (window, head).
//   scores = (Q K^T) / 8 ; softmax over keys ; O = P V
// smem: QsT[64][132], KsT[64][132] (d-major for float4 fragment reads),
//       Vs[128][64], Ss[128][132]
// ---------------------------------------------------------------------------
#define AP 132
#define ATTN_SMEM_FLOATS (64 * AP + 64 * AP + 128 * 64 + 128 * AP)
#define ATTN_SMEM_BYTES  (ATTN_SMEM_FLOATS * 4)

__global__ __launch_bounds__(256) void attn_kernel()
{
    extern __shared__ float sm[];
    float* QsT = sm;                  // [64][AP]
    float* KsT = QsT + 64 * AP;       // [64][AP]
    float* Vs  = KsT + 64 * AP;       // [128][64]
    float* Ss  = Vs  + 128 * 64;      // [128][AP]

    const int h   = blockIdx.x;
    const int wdw = blockIdx.y;
    const int t   = threadIdx.x;

    const size_t gbase = (size_t)wdw * WSZ * DM + (size_t)h * HD;

    // ---- fill Q^T, K^T, V ----
#pragma unroll
    for (int it = 0; it < 8; it++) {
        int f   = it * 256 + t;          // float4 index within 128x16(float4)
        int row = f >> 4;                // 0..127
        int c4  = (f & 15) << 2;         // 0..60 step 4
        const float* qp = g_q + gbase + (size_t)row * DM + c4;
        const float* kp = g_k + gbase + (size_t)row * DM + c4;
        const float* vp = g_v + gbase + (size_t)row * DM + c4;
        float4 qv = *(const float4*)qp;
        float4 kv = *(const float4*)kp;
        float4 vv = *(const float4*)vp;
        QsT[(c4 + 0) * AP + row] = qv.x;
        QsT[(c4 + 1) * AP + row] = qv.y;
        QsT[(c4 + 2) * AP + row] = qv.z;
        QsT[(c4 + 3) * AP + row] = qv.w;
        KsT[(c4 + 0) * AP + row] = kv.x;
        KsT[(c4 + 1) * AP + row] = kv.y;
        KsT[(c4 + 2) * AP + row] = kv.z;
        KsT[(c4 + 3) * AP + row] = kv.w;
        *(float4*)(Vs + row * HD + c4) = vv;
    }
    __syncthreads();

    // ---- phase 1: S = Q K^T * scale ----
    const int ty = t >> 4, tx = t & 15;
    const int p0 = ty << 3, q0 = tx << 3;
    float acc[8][8];
#pragma unroll
    for (int i = 0; i < 8; i++)
#pragma unroll
        for (int j = 0; j < 8; j++) acc[i][j] = 0.f;

#pragma unroll 8
    for (int d = 0; d < 64; d++) {
        float a[8], b[8];
        *(float4*)&a[0] = *(const float4*)&QsT[d * AP + p0];
        *(float4*)&a[4] = *(const float4*)&QsT[d * AP + p0 + 4];
        *(float4*)&b[0] = *(const float4*)&KsT[d * AP + q0];
        *(float4*)&b[4] = *(const float4*)&KsT[d * AP + q0 + 4];
#pragma unroll
        for (int i = 0; i < 8; i++)
#pragma unroll
            for (int j = 0; j < 8; j++)
                acc[i][j] = fmaf(a[i], b[j], acc[i][j]);
    }

    const float scale = 0.125f;   // HD^-0.5
#pragma unroll
    for (int i = 0; i < 8; i++) {
        float4 s0 = make_float4(acc[i][0] * scale, acc[i][1] * scale,
                                acc[i][2] * scale, acc[i][3] * scale);
        float4 s1 = make_float4(acc[i][4] * scale, acc[i][5] * scale,
                                acc[i][6] * scale, acc[i][7] * scale);
        *(float4*)&Ss[(p0 + i) * AP + q0]     = s0;
        *(float4*)&Ss[(p0 + i) * AP + q0 + 4] = s1;
    }
    __syncthreads();

    // ---- softmax over rows (8 warps x 16 rows) ----
    const int warp = t >> 5, lane = t & 31;
    for (int r = warp * 16; r < warp * 16 + 16; r++) {
        float* srow = Ss + r * AP;
        float v0 = srow[lane];
        float v1 = srow[lane + 32];
        float v2 = srow[lane + 64];
        float v3 = srow[lane + 96];
        float mx = fmaxf(fmaxf(v0, v1), fmaxf(v2, v3));
#pragma unroll
        for (int o = 16; o > 0; o >>= 1)
            mx = fmaxf(mx, __shfl_xor_sync(0xffffffffu, mx, o));
        float e0 = __expf(v0 - mx);
        float e1 = __expf(v1 - mx);
        float e2 = __expf(v2 - mx);
        float e3 = __expf(v3 - mx);
        float s = e0 + e1 + e2 + e3;
#pragma unroll
        for (int o = 16; o > 0; o >>= 1)
            s += __shfl_xor_sync(0xffffffffu, s, o);
        float inv = 1.f / s;
        srow[lane]      = e0 * inv;
        srow[lane + 32] = e1 * inv;
        srow[lane + 64] = e2 * inv;
        srow[lane + 96] = e3 * inv;
    }
    __syncthreads();

    // ---- phase 2: O = P V  (each thread: 8 rows x 4 cols) ----
    const int c0 = tx << 2;
    float o[8][4];
#pragma unroll
    for (int i = 0; i < 8; i++)
#pragma unroll
        for (int j = 0; j < 4; j++) o[i][j] = 0.f;

#pragma unroll 4
    for (int q = 0; q < 128; q++) {
        float vf[4];
        *(float4*)vf = *(const float4*)&Vs[q * HD + c0];
#pragma unroll
        for (int i = 0; i < 8; i++) {
            float p = Ss[(p0 + i) * AP + q];
            o[i][0] = fmaf(p, vf[0], o[i][0]);
            o[i][1] = fmaf(p, vf[1], o[i][1]);
            o[i][2] = fmaf(p, vf[2], o[i][2]);
            o[i][3] = fmaf(p, vf[3], o[i][3]);
        }
    }

#pragma unroll
    for (int i = 0; i < 8; i++) {
        float* op = g_ao + gbase + (size_t)(p0 + i) * DM + c0;
        *(float4*)op = make_float4(o[i][0], o[i][1], o[i][2], o[i][3]);
    }
}

// ---------------------------------------------------------------------------
// kernel_launch
// inputs: 0=x, 1=Wq, 2=bq, 3=Wk, 4=bk, 5=Wv, 6=bv, 7=Wp, 8=bp
// ---------------------------------------------------------------------------
extern "C" void kernel_launch(void* const* d_in, const int* in_sizes, int n_in,
                              void* d_out, int out_size)
{
    const float* x  = (const float*)d_in[0];
    const float* Wq = (const float*)d_in[1];
    const float* bq = (const float*)d_in[2];
    const float* Wk = (const float*)d_in[3];
    const float* bk = (const float*)d_in[4];
    const float* Wv = (const float*)d_in[5];
    const float* bv = (const float*)d_in[6];
    const float* Wp = (const float*)d_in[7];
    const float* bp = (const float*)d_in[8];
    float* out = (float*)d_out;

    void *pq, *pk, *pv, *pao;
    cudaGetSymbolAddress(&pq,  g_q);
    cudaGetSymbolAddress(&pk,  g_k);
    cudaGetSymbolAddress(&pv,  g_v);
    cudaGetSymbolAddress(&pao, g_ao);
    float* gq  = (float*)pq;
    float* gk  = (float*)pk;
    float* gv  = (float*)pv;
    float* gao = (float*)pao;

    cudaFuncSetAttribute(attn_kernel,
                         cudaFuncAttributeMaxDynamicSharedMemorySize,
                         ATTN_SMEM_BYTES);

    dim3 gblk(256);
    dim3 ggrid(DM / 128, MTOT / 128);   // (4, 256)

    gemm_tn<<<ggrid, gblk>>>(x, Wq, bq, gq, MTOT, DM, DM);
    gemm_tn<<<ggrid, gblk>>>(x, Wk, bk, gk, MTOT, DM, DM);
    gemm_tn<<<ggrid, gblk>>>(x, Wv, bv, gv, MTOT, DM, DM);

    dim3 agrid(HEADS, NWIN);            // (8, 256)
    attn_kernel<<<agrid, gblk, ATTN_SMEM_BYTES>>>();

    gemm_tn<<<ggrid, gblk>>>(gao, Wp, bp, out, MTOT, DM, DM);
}

// round 4
// speedup vs baseline: 2.4873x; 2.4873x over previous
#include <cuda_runtime.h>
#include <cstdint>

// Problem constants
#define MTOT   32768      // B*S
#define DM     512        // d_model
#define HEADS  8
#define HD     64
#define WSZ    128
#define NWIN   256

// ---------------------------------------------------------------------------
// Scratch (device globals; no runtime allocation allowed)
// ---------------------------------------------------------------------------
__device__ float g_q [MTOT * DM];
__device__ float g_k [MTOT * DM];
__device__ float g_v [MTOT * DM];
__device__ float g_ao[MTOT * DM];

// ---------------------------------------------------------------------------
// helpers
// ---------------------------------------------------------------------------
__device__ __forceinline__ uint32_t f2tf32(float f) {
    uint32_t r;
    asm("cvt.rna.tf32.f32 %0, %1;" : "=r"(r) : "f"(f));
    return r;
}

// mma.sync m16n8k8 tf32 (Ampere-baseline PTX; valid on plain sm_103 target)
__device__ __forceinline__ void mma8(float* d, const uint32_t* a, const uint32_t* b) {
    asm volatile(
        "mma.sync.aligned.m16n8k8.row.col.f32.tf32.tf32.f32 "
        "{%0,%1,%2,%3}, {%4,%5,%6,%7}, {%8,%9}, {%0,%1,%2,%3};"
        : "+f"(d[0]), "+f"(d[1]), "+f"(d[2]), "+f"(d[3])
        : "r"(a[0]), "r"(a[1]), "r"(a[2]), "r"(a[3]), "r"(b[0]), "r"(b[1]));
}

// ---------------------------------------------------------------------------
// tf32 tensor GEMM: C[m][n] = sum_k A[m][k]*W[n][k] + bias[n]
// A: MxK row-major, W: NxK row-major (torch Linear), C: MxN.
// CTA 128x128, 8 warps (2m x 4n), warp tile 64x32, K chunks of 32.
// SMEM holds fragments in per-lane order: conflict-free lds128/lds64.
//
// m16n8k8 tf32 fragment mapping (lane l: g=l>>2, t=l&3):
//   A: a0=(g,t) a1=(g+8,t) a2=(g,t+4) a3=(g+8,t+4)
//   B: b0=(k=t, n=g) b1=(k=t+4, n=g)
//   C: c0=(g,2t) c1=(g,2t+1) c2=(g+8,2t) c3=(g+8,2t+1)
// ---------------------------------------------------------------------------
#define KC  32           // K per smem chunk
#define KS  4            // k-steps (of 8) per chunk
#define NCH (DM / KC)    // 16

__global__ __launch_bounds__(256) void gemm_tc(
    const float* __restrict__ A, const float* __restrict__ W,
    const float* __restrict__ bias, float* __restrict__ C)
{
    // FA: [mt(8)][ks(4)][lane(32)] x uint4  = 4096 floats (16KB)
    // FB: [nt(16)][ks(4)][lane(32)] x uint2 = 4096 floats (16KB)
    __shared__ uint32_t FA[4096];
    __shared__ uint32_t FB[4096];

    const int t    = threadIdx.x;
    const int warp = t >> 5;
    const int lane = t & 31;
    const int wm   = warp >> 2;        // 0..1
    const int wn   = warp & 3;         // 0..3
    const int m0   = blockIdx.y * 128;
    const int n0   = blockIdx.x * 128;

    float acc[4][4][4];
#pragma unroll
    for (int mt = 0; mt < 4; mt++)
#pragma unroll
        for (int nt = 0; nt < 4; nt++)
#pragma unroll
            for (int r = 0; r < 4; r++) acc[mt][nt][r] = 0.f;

    for (int ch = 0; ch < NCH; ch++) {
        const int ccol = ch * KC;

        // ---- stage A fragments (each thread: 4 entries x 4 values) ----
#pragma unroll
        for (int e = 0; e < 4; e++) {
            int entry = t * 4 + e;          // 0..1023
            int l     = entry & 31;
            int mtks  = entry >> 5;         // 0..31
            int mt    = mtks >> 2, ks = mtks & 3;
            int g     = l >> 2,  tt = l & 3;
            const float* ap = A + (size_t)(m0 + mt * 16 + g) * DM + ccol + ks * 8 + tt;
            uint4 u;
            u.x = f2tf32(ap[0]);
            u.y = f2tf32(ap[8 * DM]);
            u.z = f2tf32(ap[4]);
            u.w = f2tf32(ap[8 * DM + 4]);
            *(uint4*)&FA[entry * 4] = u;
        }
        // ---- stage B fragments (each thread: 8 entries x 2 values) ----
#pragma unroll
        for (int e = 0; e < 8; e++) {
            int entry = t * 8 + e;          // 0..2047
            int l     = entry & 31;
            int ntks  = entry >> 5;         // 0..63
            int nt    = ntks >> 2, ks = ntks & 3;
            int g     = l >> 2,  tt = l & 3;
            const float* wp = W + (size_t)(n0 + nt * 8 + g) * DM + ccol + ks * 8 + tt;
            uint2 u;
            u.x = f2tf32(wp[0]);
            u.y = f2tf32(wp[4]);
            *(uint2*)&FB[entry * 2] = u;
        }
        __syncthreads();

        // ---- compute 4 k-steps ----
#pragma unroll
        for (int ks = 0; ks < 4; ks++) {
            uint32_t a[4][4], b[4][2];
#pragma unroll
            for (int mt = 0; mt < 4; mt++) {
                int entry = ((wm * 4 + mt) * 4 + ks) * 32 + lane;
                *(uint4*)a[mt] = *(const uint4*)&FA[entry * 4];
            }
#pragma unroll
            for (int nt = 0; nt < 4; nt++) {
                int entry = ((wn * 4 + nt) * 4 + ks) * 32 + lane;
                *(uint2*)b[nt] = *(const uint2*)&FB[entry * 2];
            }
#pragma unroll
            for (int mt = 0; mt < 4; mt++)
#pragma unroll
                for (int nt = 0; nt < 4; nt++)
                    mma8(acc[mt][nt], a[mt], b[nt]);
        }
        __syncthreads();
    }

    // ---- epilogue: bias add + store ----
    const int g = lane >> 2, tt = lane & 3;
#pragma unroll
    for (int mt = 0; mt < 4; mt++) {
        const int row0 = m0 + wm * 64 + mt * 16 + g;
#pragma unroll
        for (int nt = 0; nt < 4; nt++) {
            const int c = n0 + wn * 32 + nt * 8 + tt * 2;
            float b0 = bias[c], b1 = bias[c + 1];
            float* p0 = C + (size_t)row0 * DM + c;
            float* p1 = C + (size_t)(row0 + 8) * DM + c;
            *(float2*)p0 = make_float2(acc[mt][nt][0] + b0, acc[mt][nt][1] + b1);
            *(float2*)p1 = make_float2(acc[mt][nt][2] + b0, acc[mt][nt][3] + b1);
        }
    }
}

// ---------------------------------------------------------------------------
// Windowed attention (unchanged, known-good): one CTA per (window, head)
// ---------------------------------------------------------------------------
#define AP 132
#define ATTN_SMEM_FLOATS (64 * AP + 64 * AP + 128 * 64 + 128 * AP)
#define ATTN_SMEM_BYTES  (ATTN_SMEM_FLOATS * 4)

__global__ __launch_bounds__(256) void attn_kernel()
{
    extern __shared__ float smf[];
    float* QsT = smf;
    float* KsT = QsT + 64 * AP;
    float* Vs  = KsT + 64 * AP;
    float* Ss  = Vs  + 128 * 64;

    const int h   = blockIdx.x;
    const int wdw = blockIdx.y;
    const int t   = threadIdx.x;

    const size_t gbase = (size_t)wdw * WSZ * DM + (size_t)h * HD;

#pragma unroll
    for (int it = 0; it < 8; it++) {
        int f   = it * 256 + t;
        int row = f >> 4;
        int c4  = (f & 15) << 2;
        const float* qp = g_q + gbase + (size_t)row * DM + c4;
        const float* kp = g_k + gbase + (size_t)row * DM + c4;
        const float* vp = g_v + gbase + (size_t)row * DM + c4;
        float4 qv = *(const float4*)qp;
        float4 kv = *(const float4*)kp;
        float4 vv = *(const float4*)vp;
        QsT[(c4 + 0) * AP + row] = qv.x;
        QsT[(c4 + 1) * AP + row] = qv.y;
        QsT[(c4 + 2) * AP + row] = qv.z;
        QsT[(c4 + 3) * AP + row] = qv.w;
        KsT[(c4 + 0) * AP + row] = kv.x;
        KsT[(c4 + 1) * AP + row] = kv.y;
        KsT[(c4 + 2) * AP + row] = kv.z;
        KsT[(c4 + 3) * AP + row] = kv.w;
        *(float4*)(Vs + row * HD + c4) = vv;
    }
    __syncthreads();

    const int ty = t >> 4, tx = t & 15;
    const int p0 = ty << 3, q0 = tx << 3;
    float acc[8][8];
#pragma unroll
    for (int i = 0; i < 8; i++)
#pragma unroll
        for (int j = 0; j < 8; j++) acc[i][j] = 0.f;

#pragma unroll 8
    for (int d = 0; d < 64; d++) {
        float a[8], b[8];
        *(float4*)&a[0] = *(const float4*)&QsT[d * AP + p0];
        *(float4*)&a[4] = *(const float4*)&QsT[d * AP + p0 + 4];
        *(float4*)&b[0] = *(const float4*)&KsT[d * AP + q0];
        *(float4*)&b[4] = *(const float4*)&KsT[d * AP + q0 + 4];
#pragma unroll
        for (int i = 0; i < 8; i++)
#pragma unroll
            for (int j = 0; j < 8; j++)
                acc[i][j] = fmaf(a[i], b[j], acc[i][j]);
    }

    const float scale = 0.125f;
#pragma unroll
    for (int i = 0; i < 8; i++) {
        float4 s0 = make_float4(acc[i][0] * scale, acc[i][1] * scale,
                                acc[i][2] * scale, acc[i][3] * scale);
        float4 s1 = make_float4(acc[i][4] * scale, acc[i][5] * scale,
                                acc[i][6] * scale, acc[i][7] * scale);
        *(float4*)&Ss[(p0 + i) * AP + q0]     = s0;
        *(float4*)&Ss[(p0 + i) * AP + q0 + 4] = s1;
    }
    __syncthreads();

    const int warp = t >> 5, lane = t & 31;
    for (int r = warp * 16; r < warp * 16 + 16; r++) {
        float* srow = Ss + r * AP;
        float v0 = srow[lane];
        float v1 = srow[lane + 32];
        float v2 = srow[lane + 64];
        float v3 = srow[lane + 96];
        float mx = fmaxf(fmaxf(v0, v1), fmaxf(v2, v3));
#pragma unroll
        for (int o = 16; o > 0; o >>= 1)
            mx = fmaxf(mx, __shfl_xor_sync(0xffffffffu, mx, o));
        float e0 = __expf(v0 - mx);
        float e1 = __expf(v1 - mx);
        float e2 = __expf(v2 - mx);
        float e3 = __expf(v3 - mx);
        float s = e0 + e1 + e2 + e3;
#pragma unroll
        for (int o = 16; o > 0; o >>= 1)
            s += __shfl_xor_sync(0xffffffffu, s, o);
        float inv = 1.f / s;
        srow[lane]      = e0 * inv;
        srow[lane + 32] = e1 * inv;
        srow[lane + 64] = e2 * inv;
        srow[lane + 96] = e3 * inv;
    }
    __syncthreads();

    const int c0 = tx << 2;
    float o[8][4];
#pragma unroll
    for (int i = 0; i < 8; i++)
#pragma unroll
        for (int j = 0; j < 4; j++) o[i][j] = 0.f;

#pragma unroll 4
    for (int q = 0; q < 128; q++) {
        float vf[4];
        *(float4*)vf = *(const float4*)&Vs[q * HD + c0];
#pragma unroll
        for (int i = 0; i < 8; i++) {
            float p = Ss[(p0 + i) * AP + q];
            o[i][0] = fmaf(p, vf[0], o[i][0]);
            o[i][1] = fmaf(p, vf[1], o[i][1]);
            o[i][2] = fmaf(p, vf[2], o[i][2]);
            o[i][3] = fmaf(p, vf[3], o[i][3]);
        }
    }

#pragma unroll
    for (int i = 0; i < 8; i++) {
        float* op = g_ao + gbase + (size_t)(p0 + i) * DM + c0;
        *(float4*)op = make_float4(o[i][0], o[i][1], o[i][2], o[i][3]);
    }
}

// ---------------------------------------------------------------------------
// kernel_launch
// ---------------------------------------------------------------------------
extern "C" void kernel_launch(void* const* d_in, const int* in_sizes, int n_in,
                              void* d_out, int out_size)
{
    const float* x  = (const float*)d_in[0];
    const float* Wq = (const float*)d_in[1];
    const float* bq = (const float*)d_in[2];
    const float* Wk = (const float*)d_in[3];
    const float* bk = (const float*)d_in[4];
    const float* Wv = (const float*)d_in[5];
    const float* bv = (const float*)d_in[6];
    const float* Wp = (const float*)d_in[7];
    const float* bp = (const float*)d_in[8];
    float* out = (float*)d_out;

    void *pq, *pk, *pv, *pao;
    cudaGetSymbolAddress(&pq,  g_q);
    cudaGetSymbolAddress(&pk,  g_k);
    cudaGetSymbolAddress(&pv,  g_v);
    cudaGetSymbolAddress(&pao, g_ao);
    float* gq  = (float*)pq;
    float* gk  = (float*)pk;
    float* gv  = (float*)pv;
    float* gao = (float*)pao;

    cudaFuncSetAttribute(attn_kernel,
                         cudaFuncAttributeMaxDynamicSharedMemorySize, ATTN_SMEM_BYTES);

    dim3 gblk(256);
    dim3 ggrid(DM / 128, MTOT / 128);   // (4, 256)

    gemm_tc<<<ggrid, gblk>>>(x, Wq, bq, gq);
    gemm_tc<<<ggrid, gblk>>>(x, Wk, bk, gk);
    gemm_tc<<<ggrid, gblk>>>(x, Wv, bv, gv);

    dim3 agrid(HEADS, NWIN);            // (8, 256)
    attn_kernel<<<agrid, gblk, ATTN_SMEM_BYTES>>>();

    gemm_tc<<<ggrid, gblk>>>(gao, Wp, bp, out);
}

// round 6
// speedup vs baseline: 3.9718x; 1.5968x over previous
#include <cuda_runtime.h>
#include <cstdint>

// Problem constants
#define MTOT   32768      // B*S
#define DM     512        // d_model
#define HEADS  8
#define HD     64
#define WSZ    128
#define NWIN   256

// ---------------------------------------------------------------------------
// Scratch (device globals; no runtime allocation allowed)
// ---------------------------------------------------------------------------
__device__ float g_q [MTOT * DM];
__device__ float g_k [MTOT * DM];
__device__ float g_v [MTOT * DM];
__device__ float g_ao[MTOT * DM];

// ---------------------------------------------------------------------------
// helpers
// ---------------------------------------------------------------------------
__device__ __forceinline__ uint32_t f2tf32(float f) {
    uint32_t r;
    asm("cvt.rna.tf32.f32 %0, %1;" : "=r"(r) : "f"(f));
    return r;
}

// mma.sync m16n8k8 tf32 (baseline PTX; valid on plain sm_103 target)
__device__ __forceinline__ void mma8(float* d, const uint32_t* a, const uint32_t* b) {
    asm volatile(
        "mma.sync.aligned.m16n8k8.row.col.f32.tf32.tf32.f32 "
        "{%0,%1,%2,%3}, {%4,%5,%6,%7}, {%8,%9}, {%0,%1,%2,%3};"
        : "+f"(d[0]), "+f"(d[1]), "+f"(d[2]), "+f"(d[3])
        : "r"(a[0]), "r"(a[1]), "r"(a[2]), "r"(a[3]), "r"(b[0]), "r"(b[1]));
}

// ---------------------------------------------------------------------------
// tf32 tensor GEMM: C[m][n] = sum_k A[m][k]*W[n][k] + bias[n]
// CTA 128x128, 8 warps (2m x 4n), warp tile 64x32, K chunks of 32.
// Row-major smem, pitch 36 floats: fragment reads hit banks (4g+tt)%32,
// all distinct -> conflict-free. Coalesced float4 staging + register
// prefetch pipeline (LDG ch+1 issued before compute of ch).
//
// m16n8k8 tf32 fragment mapping (lane l: g=l>>2, tt=l&3):
//   A: a0=(g,tt) a1=(g+8,tt) a2=(g,tt+4) a3=(g+8,tt+4)
//   B: b0=(n=g,k=tt) b1=(n=g,k=tt+4)
//   C: c0=(g,2tt) c1=(g,2tt+1) c2=(g+8,2tt) c3=(g+8,2tt+1)
// ---------------------------------------------------------------------------
#define KC    32
#define NCH   (DM / KC)    // 16
#define PITCH 36

__global__ __launch_bounds__(256) void gemm_tc(
    const float* __restrict__ A, const float* __restrict__ W,
    const float* __restrict__ bias, float* __restrict__ C)
{
    __shared__ uint32_t As[128 * PITCH];   // 18 KB
    __shared__ uint32_t Ws[128 * PITCH];   // 18 KB

    const int t    = threadIdx.x;
    const int warp = t >> 5;
    const int lane = t & 31;
    const int wm   = warp >> 2;        // 0..1
    const int wn   = warp & 3;         // 0..3
    const int g    = lane >> 2;
    const int tt   = lane & 3;
    const int m0   = blockIdx.y * 128;
    const int n0   = blockIdx.x * 128;

    // staging coords: f = e*256+t ; row = f>>3 ; colq = f&7  (coalesced)
    int srow[4], scolq[4];
#pragma unroll
    for (int e = 0; e < 4; e++) {
        int f = e * 256 + t;
        srow[e]  = f >> 3;
        scolq[e] = f & 7;
    }

    float acc[4][4][4];
#pragma unroll
    for (int mt = 0; mt < 4; mt++)
#pragma unroll
        for (int nt = 0; nt < 4; nt++)
#pragma unroll
            for (int r = 0; r < 4; r++) acc[mt][nt][r] = 0.f;

    // prologue: prefetch chunk 0
    float4 pa[4], pw[4];
#pragma unroll
    for (int e = 0; e < 4; e++) {
        pa[e] = *(const float4*)(A + (size_t)(m0 + srow[e]) * DM + scolq[e] * 4);
        pw[e] = *(const float4*)(W + (size_t)(n0 + srow[e]) * DM + scolq[e] * 4);
    }

    for (int ch = 0; ch < NCH; ch++) {
        // store prefetched chunk (convert to tf32, round-to-nearest)
#pragma unroll
        for (int e = 0; e < 4; e++) {
            uint4 ua = make_uint4(f2tf32(pa[e].x), f2tf32(pa[e].y),
                                  f2tf32(pa[e].z), f2tf32(pa[e].w));
            uint4 uw = make_uint4(f2tf32(pw[e].x), f2tf32(pw[e].y),
                                  f2tf32(pw[e].z), f2tf32(pw[e].w));
            *(uint4*)&As[srow[e] * PITCH + scolq[e] * 4] = ua;
            *(uint4*)&Ws[srow[e] * PITCH + scolq[e] * 4] = uw;
        }
        __syncthreads();

        // prefetch next chunk (in flight during compute below)
        if (ch + 1 < NCH) {
            const int ccol = (ch + 1) * KC;
#pragma unroll
            for (int e = 0; e < 4; e++) {
                pa[e] = *(const float4*)(A + (size_t)(m0 + srow[e]) * DM + ccol + scolq[e] * 4);
                pw[e] = *(const float4*)(W + (size_t)(n0 + srow[e]) * DM + ccol + scolq[e] * 4);
            }
        }

        // compute 4 k-steps
#pragma unroll
        for (int ks = 0; ks < 4; ks++) {
            uint32_t a[4][4], b[4][2];
#pragma unroll
            for (int mt = 0; mt < 4; mt++) {
                int ar = (wm * 64 + mt * 16 + g) * PITCH + ks * 8 + tt;
                a[mt][0] = As[ar];
                a[mt][1] = As[ar + 8 * PITCH];
                a[mt][2] = As[ar + 4];
                a[mt][3] = As[ar + 8 * PITCH + 4];
            }
#pragma unroll
            for (int nt = 0; nt < 4; nt++) {
                int br = (wn * 32 + nt * 8 + g) * PITCH + ks * 8 + tt;
                b[nt][0] = Ws[br];
                b[nt][1] = Ws[br + 4];
            }
#pragma unroll
            for (int mt = 0; mt < 4; mt++)
#pragma unroll
                for (int nt = 0; nt < 4; nt++)
                    mma8(acc[mt][nt], a[mt], b[nt]);
        }
        __syncthreads();
    }

    // epilogue: bias add + store
#pragma unroll
    for (int mt = 0; mt < 4; mt++) {
        const int row0 = m0 + wm * 64 + mt * 16 + g;
#pragma unroll
        for (int nt = 0; nt < 4; nt++) {
            const int c = n0 + wn * 32 + nt * 8 + tt * 2;
            float b0 = bias[c], b1 = bias[c + 1];
            float* p0 = C + (size_t)row0 * DM + c;
            float* p1 = C + (size_t)(row0 + 8) * DM + c;
            *(float2*)p0 = make_float2(acc[mt][nt][0] + b0, acc[mt][nt][1] + b1);
            *(float2*)p1 = make_float2(acc[mt][nt][2] + b0, acc[mt][nt][3] + b1);
        }
    }
}

// ---------------------------------------------------------------------------
// Windowed attention: one CTA per (window, head).
// Smem aliasing: Ss (128x132) reuses the QsT/KsT (2x 64x132) region after
// phase 1 -> 100KB total -> 2 CTAs/SM.
// ---------------------------------------------------------------------------
#define AP 132
#define ATTN_SMEM_FLOATS (128 * AP + 128 * 64)
#define ATTN_SMEM_BYTES  (ATTN_SMEM_FLOATS * 4)

__global__ __launch_bounds__(256) void attn_kernel()
{
    extern __shared__ float smf[];
    float* QsT = smf;                 // [64][AP]
    float* KsT = smf + 64 * AP;       // [64][AP]
    float* Ss  = smf;                 // [128][AP]  (aliases QsT+KsT)
    float* Vs  = smf + 128 * AP;      // [128][64]

    const int h   = blockIdx.x;
    const int wdw = blockIdx.y;
    const int t   = threadIdx.x;

    const size_t gbase = (size_t)wdw * WSZ * DM + (size_t)h * HD;

#pragma unroll
    for (int it = 0; it < 8; it++) {
        int f   = it * 256 + t;
        int row = f >> 4;
        int c4  = (f & 15) << 2;
        const float* qp = g_q + gbase + (size_t)row * DM + c4;
        const float* kp = g_k + gbase + (size_t)row * DM + c4;
        const float* vp = g_v + gbase + (size_t)row * DM + c4;
        float4 qv = *(const float4*)qp;
        float4 kv = *(const float4*)kp;
        float4 vv = *(const float4*)vp;
        QsT[(c4 + 0) * AP + row] = qv.x;
        QsT[(c4 + 1) * AP + row] = qv.y;
        QsT[(c4 + 2) * AP + row] = qv.z;
        QsT[(c4 + 3) * AP + row] = qv.w;
        KsT[(c4 + 0) * AP + row] = kv.x;
        KsT[(c4 + 1) * AP + row] = kv.y;
        KsT[(c4 + 2) * AP + row] = kv.z;
        KsT[(c4 + 3) * AP + row] = kv.w;
        *(float4*)(Vs + row * HD + c4) = vv;
    }
    __syncthreads();

    const int ty = t >> 4, tx = t & 15;
    const int p0 = ty << 3, q0 = tx << 3;
    float acc[8][8];
#pragma unroll
    for (int i = 0; i < 8; i++)
#pragma unroll
        for (int j = 0; j < 8; j++) acc[i][j] = 0.f;

#pragma unroll 8
    for (int d = 0; d < 64; d++) {
        float a[8], b[8];
        *(float4*)&a[0] = *(const float4*)&QsT[d * AP + p0];
        *(float4*)&a[4] = *(const float4*)&QsT[d * AP + p0 + 4];
        *(float4*)&b[0] = *(const float4*)&KsT[d * AP + q0];
        *(float4*)&b[4] = *(const float4*)&KsT[d * AP + q0 + 4];
#pragma unroll
        for (int i = 0; i < 8; i++)
#pragma unroll
            for (int j = 0; j < 8; j++)
                acc[i][j] = fmaf(a[i], b[j], acc[i][j]);
    }
    __syncthreads();   // all QsT/KsT reads done before Ss overwrites them

    const float scale = 0.125f;
#pragma unroll
    for (int i = 0; i < 8; i++) {
        float4 s0 = make_float4(acc[i][0] * scale, acc[i][1] * scale,
                                acc[i][2] * scale, acc[i][3] * scale);
        float4 s1 = make_float4(acc[i][4] * scale, acc[i][5] * scale,
                                acc[i][6] * scale, acc[i][7] * scale);
        *(float4*)&Ss[(p0 + i) * AP + q0]     = s0;
        *(float4*)&Ss[(p0 + i) * AP + q0 + 4] = s1;
    }
    __syncthreads();

    const int warp = t >> 5, lane = t & 31;
    for (int r = warp * 16; r < warp * 16 + 16; r++) {
        float* srow = Ss + r * AP;
        float v0 = srow[lane];
        float v1 = srow[lane + 32];
        float v2 = srow[lane + 64];
        float v3 = srow[lane + 96];
        float mx = fmaxf(fmaxf(v0, v1), fmaxf(v2, v3));
#pragma unroll
        for (int o = 16; o > 0; o >>= 1)
            mx = fmaxf(mx, __shfl_xor_sync(0xffffffffu, mx, o));
        float e0 = __expf(v0 - mx);
        float e1 = __expf(v1 - mx);
        float e2 = __expf(v2 - mx);
        float e3 = __expf(v3 - mx);
        float s = e0 + e1 + e2 + e3;
#pragma unroll
        for (int o = 16; o > 0; o >>= 1)
            s += __shfl_xor_sync(0xffffffffu, s, o);
        float inv = 1.f / s;
        srow[lane]      = e0 * inv;
        srow[lane + 32] = e1 * inv;
        srow[lane + 64] = e2 * inv;
        srow[lane + 96] = e3 * inv;
    }
    __syncthreads();

    const int c0 = tx << 2;
    float o[8][4];
#pragma unroll
    for (int i = 0; i < 8; i++)
#pragma unroll
        for (int j = 0; j < 4; j++) o[i][j] = 0.f;

#pragma unroll 4
    for (int q = 0; q < 128; q++) {
        float vf[4];
        *(float4*)vf = *(const float4*)&Vs[q * HD + c0];
#pragma unroll
        for (int i = 0; i < 8; i++) {
            float p = Ss[(p0 + i) * AP + q];
            o[i][0] = fmaf(p, vf[0], o[i][0]);
            o[i][1] = fmaf(p, vf[1], o[i][1]);
            o[i][2] = fmaf(p, vf[2], o[i][2]);
            o[i][3] = fmaf(p, vf[3], o[i][3]);
        }
    }

#pragma unroll
    for (int i = 0; i < 8; i++) {
        float* op = g_ao + gbase + (size_t)(p0 + i) * DM + c0;
        *(float4*)op = make_float4(o[i][0], o[i][1], o[i][2], o[i][3]);
    }
}

// ---------------------------------------------------------------------------
// kernel_launch
// ---------------------------------------------------------------------------
extern "C" void kernel_launch(void* const* d_in, const int* in_sizes, int n_in,
                              void* d_out, int out_size)
{
    const float* x  = (const float*)d_in[0];
    const float* Wq = (const float*)d_in[1];
    const float* bq = (const float*)d_in[2];
    const float* Wk = (const float*)d_in[3];
    const float* bk = (const float*)d_in[4];
    const float* Wv = (const float*)d_in[5];
    const float* bv = (const float*)d_in[6];
    const float* Wp = (const float*)d_in[7];
    const float* bp = (const float*)d_in[8];
    float* out = (float*)d_out;

    void *pq, *pk, *pv, *pao;
    cudaGetSymbolAddress(&pq,  g_q);
    cudaGetSymbolAddress(&pk,  g_k);
    cudaGetSymbolAddress(&pv,  g_v);
    cudaGetSymbolAddress(&pao, g_ao);
    float* gq  = (float*)pq;
    float* gk  = (float*)pk;
    float* gv  = (float*)pv;
    float* gao = (float*)pao;

    cudaFuncSetAttribute(attn_kernel,
                         cudaFuncAttributeMaxDynamicSharedMemorySize, ATTN_SMEM_BYTES);

    dim3 gblk(256);
    dim3 ggrid(DM / 128, MTOT / 128);   // (4, 256)

    gemm_tc<<<ggrid, gblk>>>(x, Wq, bq, gq);
    gemm_tc<<<ggrid, gblk>>>(x, Wk, bk, gk);
    gemm_tc<<<ggrid, gblk>>>(x, Wv, bv, gv);

    dim3 agrid(HEADS, NWIN);            // (8, 256)
    attn_kernel<<<agrid, gblk, ATTN_SMEM_BYTES>>>();

    gemm_tc<<<ggrid, gblk>>>(gao, Wp, bp, out);
}

// round 8
// speedup vs baseline: 4.6879x; 1.1803x over previous
#include <cuda_runtime.h>
#include <cstdint>

// Problem constants
#define MTOT   32768      // B*S
#define DM     512        // d_model
#define HEADS  8
#define HD     64
#define WSZ    128
#define NWIN   256

// ---------------------------------------------------------------------------
// Scratch (device globals; no runtime allocation allowed)
// ---------------------------------------------------------------------------
__device__ float g_q [MTOT * DM];
__device__ float g_k [MTOT * DM];
__device__ float g_v [MTOT * DM];
__device__ float g_ao[MTOT * DM];

// ---------------------------------------------------------------------------
// helpers
// ---------------------------------------------------------------------------
__device__ __forceinline__ uint32_t f2tf32(float f) {
    uint32_t r;
    asm("cvt.rna.tf32.f32 %0, %1;" : "=r"(r) : "f"(f));
    return r;
}

// mma.sync m16n8k8 tf32 (baseline PTX; valid on plain sm_103 target)
__device__ __forceinline__ void mma8(float* d, const uint32_t* a, const uint32_t* b) {
    asm volatile(
        "mma.sync.aligned.m16n8k8.row.col.f32.tf32.tf32.f32 "
        "{%0,%1,%2,%3}, {%4,%5,%6,%7}, {%8,%9}, {%0,%1,%2,%3};"
        : "+f"(d[0]), "+f"(d[1]), "+f"(d[2]), "+f"(d[3])
        : "r"(a[0]), "r"(a[1]), "r"(a[2]), "r"(a[3]), "r"(b[0]), "r"(b[1]));
}

// Fast exp on FMA/ALU pipes only (no MUFU, no CVT).
// x <= 0 here (post max-subtraction); |y| < 2^21 so the magic trick is exact.
__device__ __forceinline__ float fexp(float x) {
    float y = x * 1.44269504088896f;          // log2(e)
    float t = y + 12582912.f;                 // 2^23 + 2^22 round trick
    float n = t - 12582912.f;
    float f = y - n;
    float p = 0.00133335581f;                 // 2^f Taylor, |f| <= 0.5
    p = fmaf(p, f, 0.00961812910f);
    p = fmaf(p, f, 0.05550410866f);
    p = fmaf(p, f, 0.24022650696f);
    p = fmaf(p, f, 0.69314718056f);
    p = fmaf(p, f, 1.0f);
    int ni = __float_as_int(t) - 0x4B400000;  // integer n
    float s = __int_as_float((ni + 127) << 23);
    return p * s;
}

// ---------------------------------------------------------------------------
// tf32 tensor GEMM (unchanged from round 5): C = A*W^T + bias
// ---------------------------------------------------------------------------
#define KC    32
#define NCH   (DM / KC)    // 16
#define PITCH 36

__global__ __launch_bounds__(256) void gemm_tc(
    const float* __restrict__ A, const float* __restrict__ W,
    const float* __restrict__ bias, float* __restrict__ C)
{
    __shared__ uint32_t As[128 * PITCH];
    __shared__ uint32_t Ws[128 * PITCH];

    const int t    = threadIdx.x;
    const int warp = t >> 5;
    const int lane = t & 31;
    const int wm   = warp >> 2;
    const int wn   = warp & 3;
    const int g    = lane >> 2;
    const int tt   = lane & 3;
    const int m0   = blockIdx.y * 128;
    const int n0   = blockIdx.x * 128;

    int srow[4], scolq[4];
#pragma unroll
    for (int e = 0; e < 4; e++) {
        int f = e * 256 + t;
        srow[e]  = f >> 3;
        scolq[e] = f & 7;
    }

    float acc[4][4][4];
#pragma unroll
    for (int mt = 0; mt < 4; mt++)
#pragma unroll
        for (int nt = 0; nt < 4; nt++)
#pragma unroll
            for (int r = 0; r < 4; r++) acc[mt][nt][r] = 0.f;

    float4 pa[4], pw[4];
#pragma unroll
    for (int e = 0; e < 4; e++) {
        pa[e] = *(const float4*)(A + (size_t)(m0 + srow[e]) * DM + scolq[e] * 4);
        pw[e] = *(const float4*)(W + (size_t)(n0 + srow[e]) * DM + scolq[e] * 4);
    }

    for (int ch = 0; ch < NCH; ch++) {
#pragma unroll
        for (int e = 0; e < 4; e++) {
            uint4 ua = make_uint4(f2tf32(pa[e].x), f2tf32(pa[e].y),
                                  f2tf32(pa[e].z), f2tf32(pa[e].w));
            uint4 uw = make_uint4(f2tf32(pw[e].x), f2tf32(pw[e].y),
                                  f2tf32(pw[e].z), f2tf32(pw[e].w));
            *(uint4*)&As[srow[e] * PITCH + scolq[e] * 4] = ua;
            *(uint4*)&Ws[srow[e] * PITCH + scolq[e] * 4] = uw;
        }
        __syncthreads();

        if (ch + 1 < NCH) {
            const int ccol = (ch + 1) * KC;
#pragma unroll
            for (int e = 0; e < 4; e++) {
                pa[e] = *(const float4*)(A + (size_t)(m0 + srow[e]) * DM + ccol + scolq[e] * 4);
                pw[e] = *(const float4*)(W + (size_t)(n0 + srow[e]) * DM + ccol + scolq[e] * 4);
            }
        }

#pragma unroll
        for (int ks = 0; ks < 4; ks++) {
            uint32_t a[4][4], b[4][2];
#pragma unroll
            for (int mt = 0; mt < 4; mt++) {
                int ar = (wm * 64 + mt * 16 + g) * PITCH + ks * 8 + tt;
                a[mt][0] = As[ar];
                a[mt][1] = As[ar + 8 * PITCH];
                a[mt][2] = As[ar + 4];
                a[mt][3] = As[ar + 8 * PITCH + 4];
            }
#pragma unroll
            for (int nt = 0; nt < 4; nt++) {
                int br = (wn * 32 + nt * 8 + g) * PITCH + ks * 8 + tt;
                b[nt][0] = Ws[br];
                b[nt][1] = Ws[br + 4];
            }
#pragma unroll
            for (int mt = 0; mt < 4; mt++)
#pragma unroll
                for (int nt = 0; nt < 4; nt++)
                    mma8(acc[mt][nt], a[mt], b[nt]);
        }
        __syncthreads();
    }

#pragma unroll
    for (int mt = 0; mt < 4; mt++) {
        const int row0 = m0 + wm * 64 + mt * 16 + g;
#pragma unroll
        for (int nt = 0; nt < 4; nt++) {
            const int c = n0 + wn * 32 + nt * 8 + tt * 2;
            float b0 = bias[c], b1 = bias[c + 1];
            float* p0 = C + (size_t)row0 * DM + c;
            float* p1 = C + (size_t)(row0 + 8) * DM + c;
            *(float2*)p0 = make_float2(acc[mt][nt][0] + b0, acc[mt][nt][1] + b1);
            *(float2*)p1 = make_float2(acc[mt][nt][2] + b0, acc[mt][nt][3] + b1);
        }
    }
}

// ---------------------------------------------------------------------------
// Windowed attention v2: tensor-core matmuls + FMA-pipe softmax.
// One CTA per (window, head). 8 warps as 2(m) x 4(n).
//   S = Q K^T (128x128x64, tf32 mma), softmax (poly exp), O = P V (128x64x128).
// Smem: Qs[128][68], Ks[128][68] (tf32), aliased by Ss[128][132] (fp32/P tf32),
//       Vs[128][68] (tf32). Total 104448 B -> 2 CTAs/SM.
// ---------------------------------------------------------------------------
#define QP 68
#define SP 132
#define ATTN_SMEM_BYTES ((2 * 128 * QP + 128 * QP) * 4)   // 104448

__global__ __launch_bounds__(256, 2) void attn_kernel()
{
    extern __shared__ float smf[];
    float*    Qsf = smf;                       // [128][QP]
    float*    Ksf = smf + 128 * QP;            // [128][QP]
    uint32_t* Qs  = (uint32_t*)Qsf;
    uint32_t* Ks  = (uint32_t*)Ksf;
    float*    Ss  = smf;                       // [128][SP] aliases Qs+Ks
    uint32_t* Ssu = (uint32_t*)Ss;
    float*    Vsf = smf + 2 * 128 * QP;        // [128][QP]
    uint32_t* Vs  = (uint32_t*)Vsf;

    const int h    = blockIdx.x;
    const int wdw  = blockIdx.y;
    const int t    = threadIdx.x;
    const int warp = t >> 5;
    const int lane = t & 31;
    const int wm   = warp >> 2;     // 0..1
    const int wn   = warp & 3;      // 0..3
    const int g    = lane >> 2;
    const int tt   = lane & 3;

    const size_t gbase = (size_t)wdw * WSZ * DM + (size_t)h * HD;

    // ---- stage Q, K, V as tf32 (row-major, pitch QP) ----
#pragma unroll
    for (int it = 0; it < 8; it++) {
        int f   = it * 256 + t;          // 2048 float4s per tensor
        int row = f >> 4;
        int c4  = (f & 15) << 2;
        const float* qp = g_q + gbase + (size_t)row * DM + c4;
        const float* kp = g_k + gbase + (size_t)row * DM + c4;
        const float* vp = g_v + gbase + (size_t)row * DM + c4;
        float4 qv = *(const float4*)qp;
        float4 kv = *(const float4*)kp;
        float4 vv = *(const float4*)vp;
        *(uint4*)&Qs[row * QP + c4] =
            make_uint4(f2tf32(qv.x), f2tf32(qv.y), f2tf32(qv.z), f2tf32(qv.w));
        *(uint4*)&Ks[row * QP + c4] =
            make_uint4(f2tf32(kv.x), f2tf32(kv.y), f2tf32(kv.z), f2tf32(kv.w));
        *(uint4*)&Vs[row * QP + c4] =
            make_uint4(f2tf32(vv.x), f2tf32(vv.y), f2tf32(vv.z), f2tf32(vv.w));
    }
    __syncthreads();

    // ---- phase 1: S = Q K^T  (warp tile 64x32, 8 k-steps) ----
    float sacc[4][4][4];
#pragma unroll
    for (int mt = 0; mt < 4; mt++)
#pragma unroll
        for (int nt = 0; nt < 4; nt++)
#pragma unroll
            for (int r = 0; r < 4; r++) sacc[mt][nt][r] = 0.f;

#pragma unroll
    for (int ks = 0; ks < 8; ks++) {
        uint32_t a[4][4], b[4][2];
#pragma unroll
        for (int mt = 0; mt < 4; mt++) {
            int ar = (wm * 64 + mt * 16 + g) * QP + ks * 8 + tt;
            a[mt][0] = Qs[ar];
            a[mt][1] = Qs[ar + 8 * QP];
            a[mt][2] = Qs[ar + 4];
            a[mt][3] = Qs[ar + 8 * QP + 4];
        }
#pragma unroll
        for (int nt = 0; nt < 4; nt++) {
            int br = (wn * 32 + nt * 8 + g) * QP + ks * 8 + tt;
            b[nt][0] = Ks[br];
            b[nt][1] = Ks[br + 4];
        }
#pragma unroll
        for (int mt = 0; mt < 4; mt++)
#pragma unroll
            for (int nt = 0; nt < 4; nt++)
                mma8(sacc[mt][nt], a[mt], b[nt]);
    }
    __syncthreads();   // Qs/Ks reads complete before Ss overwrite

    // ---- write scaled scores to Ss ----
    const float scale = 0.125f;
#pragma unroll
    for (int mt = 0; mt < 4; mt++) {
        int r0 = (wm * 64 + mt * 16 + g) * SP;
        int r1 = r0 + 8 * SP;
#pragma unroll
        for (int nt = 0; nt < 4; nt++) {
            int c = wn * 32 + nt * 8 + tt * 2;
            Ss[r0 + c]     = sacc[mt][nt][0] * scale;
            Ss[r0 + c + 1] = sacc[mt][nt][1] * scale;
            Ss[r1 + c]     = sacc[mt][nt][2] * scale;
            Ss[r1 + c + 1] = sacc[mt][nt][3] * scale;
        }
    }
    __syncthreads();

    // ---- softmax (poly exp on FMA pipe), write P rounded to tf32 ----
    for (int r = warp * 16; r < warp * 16 + 16; r++) {
        float* srow = Ss + r * SP;
        float v0 = srow[lane];
        float v1 = srow[lane + 32];
        float v2 = srow[lane + 64];
        float v3 = srow[lane + 96];
        float mx = fmaxf(fmaxf(v0, v1), fmaxf(v2, v3));
#pragma unroll
        for (int o = 16; o > 0; o >>= 1)
            mx = fmaxf(mx, __shfl_xor_sync(0xffffffffu, mx, o));
        float e0 = fexp(v0 - mx);
        float e1 = fexp(v1 - mx);
        float e2 = fexp(v2 - mx);
        float e3 = fexp(v3 - mx);
        float s = e0 + e1 + e2 + e3;
#pragma unroll
        for (int o = 16; o > 0; o >>= 1)
            s += __shfl_xor_sync(0xffffffffu, s, o);
        float inv = 1.f / s;
        uint32_t* urow = (uint32_t*)srow;
        urow[lane]      = f2tf32(e0 * inv);
        urow[lane + 32] = f2tf32(e1 * inv);
        urow[lane + 64] = f2tf32(e2 * inv);
        urow[lane + 96] = f2tf32(e3 * inv);
    }
    __syncthreads();

    // ---- phase 2: O = P V  (warp tile 64x16, 16 k-steps) ----
    float oacc[4][2][4];
#pragma unroll
    for (int mt = 0; mt < 4; mt++)
#pragma unroll
        for (int nt = 0; nt < 2; nt++)
#pragma unroll
            for (int r = 0; r < 4; r++) oacc[mt][nt][r] = 0.f;

#pragma unroll
    for (int ks = 0; ks < 16; ks++) {
        uint32_t a[4][4], b[2][2];
#pragma unroll
        for (int mt = 0; mt < 4; mt++) {
            int ar = (wm * 64 + mt * 16 + g) * SP + ks * 8 + tt;
            a[mt][0] = Ssu[ar];
            a[mt][1] = Ssu[ar + 8 * SP];
            a[mt][2] = Ssu[ar + 4];
            a[mt][3] = Ssu[ar + 8 * SP + 4];
        }
#pragma unroll
        for (int nt = 0; nt < 2; nt++) {
            int br = (ks * 8 + tt) * QP + wn * 16 + nt * 8 + g;
            b[nt][0] = Vs[br];
            b[nt][1] = Vs[br + 4 * QP];
        }
#pragma unroll
        for (int mt = 0; mt < 4; mt++)
#pragma unroll
            for (int nt = 0; nt < 2; nt++)
                mma8(oacc[mt][nt], a[mt], b[nt]);
    }

    // ---- write O ----
#pragma unroll
    for (int mt = 0; mt < 4; mt++) {
        const int row0 = wm * 64 + mt * 16 + g;
#pragma unroll
        for (int nt = 0; nt < 2; nt++) {
            const int c = wn * 16 + nt * 8 + tt * 2;
            float* p0 = g_ao + gbase + (size_t)row0 * DM + c;
            float* p1 = g_ao + gbase + (size_t)(row0 + 8) * DM + c;
            *(float2*)p0 = make_float2(oacc[mt][nt][0], oacc[mt][nt][1]);
            *(float2*)p1 = make_float2(oacc[mt][nt][2], oacc[mt][nt][3]);
        }
    }
}

// ---------------------------------------------------------------------------
// kernel_launch
// ---------------------------------------------------------------------------
extern "C" void kernel_launch(void* const* d_in, const int* in_sizes, int n_in,
                              void* d_out, int out_size)
{
    const float* x  = (const float*)d_in[0];
    const float* Wq = (const float*)d_in[1];
    const float* bq = (const float*)d_in[2];
    const float* Wk = (const float*)d_in[3];
    const float* bk = (const float*)d_in[4];
    const float* Wv = (const float*)d_in[5];
    const float* bv = (const float*)d_in[6];
    const float* Wp = (const float*)d_in[7];
    const float* bp = (const float*)d_in[8];
    float* out = (float*)d_out;

    void *pq, *pk, *pv, *pao;
    cudaGetSymbolAddress(&pq,  g_q);
    cudaGetSymbolAddress(&pk,  g_k);
    cudaGetSymbolAddress(&pv,  g_v);
    cudaGetSymbolAddress(&pao, g_ao);
    float* gq  = (float*)pq;
    float* gk  = (float*)pk;
    float* gv  = (float*)pv;
    float* gao = (float*)pao;

    cudaFuncSetAttribute(attn_kernel,
                         cudaFuncAttributeMaxDynamicSharedMemorySize, ATTN_SMEM_BYTES);

    dim3 gblk(256);
    dim3 ggrid(DM / 128, MTOT / 128);   // (4, 256)

    gemm_tc<<<ggrid, gblk>>>(x, Wq, bq, gq);
    gemm_tc<<<ggrid, gblk>>>(x, Wk, bk, gk);
    gemm_tc<<<ggrid, gblk>>>(x, Wv, bv, gv);

    dim3 agrid(HEADS, NWIN);            // (8, 256)
    attn_kernel<<<agrid, gblk, ATTN_SMEM_BYTES>>>();

    gemm_tc<<<ggrid, gblk>>>(gao, Wp, bp, out);
}